// round 17
// baseline (speedup 1.0000x reference)
#include <cuda_runtime.h>
#include <cuda_fp16.h>
#include <cstdint>

#define BATCH   32768
#define NUM_IN  256
#define NUM_HID 512
#define NUM_OUT 64
#define M_NODES 576
#define N_NODES 832
#define KFAN    32
#define COLS    64             // batch columns per block (32 half2 words)
#define WPN     32             // u32 words per node row
#define THREADS 512            // 16 warps
#define SLOTS   16             // nodes per round (1 per warp)
#define RSTRIDE 800            // words/round: 256 src16 + 512 w_h2 + 16 bias + 16 tgt
#define RMAX    576
#define DUMMY   576            // dummy pred index, level pinned 0

// round-major param blob, per round r at r*RSTRIDE:
//   [0..256)   src16: two u16 (pred*WPN) word-offsets per u32 (slot*16 + j)
//   [256..768) w_h2:  u32 = half2 {w,w}
//   [768..784) bias per slot (f32)
//   [784..800) target word-offset per slot (int), -1 = dummy
__device__ float g_blob[(size_t)RMAX * RSTRIDE];
__device__ int   g_sched[RMAX * SLOTS];
__device__ int   g_nrounds;

// ---------------------------------------------------------------------------
// Kernel A: depth-bounded dataflow levels. lev[] init -1; per pass each
// unfinalized thread scans only its still-pending preds (bitmask), finalizes
// when all resolved; one __syncthreads_or per pass. Passes = depth + 1.
// ---------------------------------------------------------------------------
__global__ __launch_bounds__(M_NODES)
void schedule_kernel(const int* __restrict__ src) {
    __shared__ int lev[DUMMY + 32];       // [576..) dummy rows pinned 0
    __shared__ int cnt[M_NODES + 1];
    __shared__ int rbase[M_NODES + 1];
    __shared__ int pos[M_NODES + 1];
    __shared__ int lmax, R_sh;

    const int t = threadIdx.x;

    int p[KFAN];
    #pragma unroll
    for (int k = 0; k < KFAN; k++) {
        int s = __ldg(&src[t * KFAN + k]);
        p[k] = (s >= NUM_IN) ? (s - NUM_IN) : DUMMY;
    }
    lev[t] = -1;
    if (t < 32) lev[DUMMY + t] = 0;
    for (int i = t; i <= M_NODES; i += M_NODES) { cnt[i] = 0; pos[i] = 0; }
    if (t == 0) lmax = 0;
    __syncthreads();

    {
        unsigned pend = 0xFFFFFFFFu;      // all 32 preds unresolved
        int m = 0;
        bool done = false;
        while (true) {
            if (!done) {
                unsigned rem = pend;
                while (rem) {
                    int k = __ffs(rem) - 1;
                    rem &= rem - 1;
                    int l = lev[p[k]];
                    if (l >= 0) {
                        pend &= ~(1u << k);
                        m = (l > m) ? l : m;
                    }
                }
                if (pend == 0) { lev[t] = m + 1; done = true; }
            }
            if (!__syncthreads_or(!done)) break;
        }
    }

    atomicAdd(&cnt[lev[t]], 1);
    atomicMax(&lmax, lev[t]);
    __syncthreads();

    if (t == 0) {
        int r = 0;
        for (int L = 1; L <= lmax; L++) { rbase[L] = r; r += (cnt[L] + SLOTS - 1) >> 4; }
        R_sh = r;
        g_nrounds = r;
    }
    __syncthreads();

    for (int i = t; i < R_sh * SLOTS; i += M_NODES) g_sched[i] = -1;
    __syncthreads();

    {
        int L = lev[t];
        int q = atomicAdd(&pos[L], 1);
        g_sched[(rbase[L] + (q >> 4)) * SLOTS + (q & 15)] = t;
    }
}

// ---------------------------------------------------------------------------
// Kernel B: grid-parallel blob fill, one block per (used) round.  (= R11)
// ---------------------------------------------------------------------------
__global__ __launch_bounds__(256)
void blob_fill_kernel(const int* __restrict__ src,
                      const float* __restrict__ w,
                      const float* __restrict__ bias) {
    const int r = blockIdx.x;
    if (r >= g_nrounds) return;
    float* Pr = g_blob + (size_t)r * RSTRIDE;
    const int tid = threadIdx.x;

    {   // src16: premultiplied (pred * WPN) offsets
        int slot = tid >> 4, j = tid & 15;
        int nd = g_sched[r * SLOTS + slot];
        unsigned v = 0;
        if (nd >= 0) {
            unsigned a = (unsigned)src[nd * KFAN + 2 * j] * WPN;
            unsigned b = (unsigned)src[nd * KFAN + 2 * j + 1] * WPN;
            v = (a & 0xFFFFu) | (b << 16);
        }
        ((unsigned*)Pr)[slot * 16 + j] = v;
    }
    #pragma unroll
    for (int u = 0; u < 2; u++) {
        int q = tid + u * 256;
        int slot = q >> 5, k = q & 31;
        int nd = g_sched[r * SLOTS + slot];
        float wv = (nd >= 0) ? w[nd * KFAN + k] : 0.0f;
        __half2 h2 = __half2half2(__float2half_rn(wv));
        ((uint32_t*)Pr)[256 + slot * 32 + k] = *(uint32_t*)&h2;
    }
    if (tid < SLOTS) {
        int nd = g_sched[r * SLOTS + tid];
        Pr[768 + tid] = (nd >= 0) ? bias[nd] : 0.0f;
        ((int*)Pr)[784 + tid] = (nd >= 0) ? (NUM_IN + nd) * WPN : -1;
    }
}

// ---------------------------------------------------------------------------
// Main kernel (byte-identical to R11 champion): 512 blocks x 512 threads,
// 2 blocks/SM, half2 state, HFMA2 inner product, double-buffered params.
// ---------------------------------------------------------------------------
#define ST_WORDS    (N_NODES * WPN)                // 26624 u32
#define STAGE_WORDS 2112                           // 64x33 f32 staging >= 2*RSTRIDE
#define TOTAL_WORDS (ST_WORDS + STAGE_WORDS)       // 28736 -> 114944 B

extern __shared__ float smem_f[];

__device__ __forceinline__ void cp16(void* sdst, const void* gsrc) {
    uint32_t s = (uint32_t)__cvta_generic_to_shared(sdst);
    asm volatile("cp.async.cg.shared.global [%0], [%1], 16;\n" :: "r"(s), "l"(gsrc));
}

__device__ __forceinline__ __half2 u2h(uint32_t u) { return *(__half2*)&u; }

__global__ __launch_bounds__(THREADS, 2)
void neat_main_kernel(const float* __restrict__ x,
                      float* __restrict__ out) {
    uint32_t* st   = (uint32_t*)smem_f;            // [N_NODES][WPN] half2 words
    float*   stage = smem_f + ST_WORDS;            // staging / param double buffer

    const int tid  = threadIdx.x;
    const int wid  = tid >> 5;
    const int lane = tid & 31;
    const int b0   = blockIdx.x * COLS;
    const int R    = g_nrounds;

    // ---- input: x[b][n] f32 -> st[n] half2-packed; 8 chunks of 32 inputs ----
    for (int ch = 0; ch < 8; ch++) {
        const int nc0 = ch * 32;
        __syncthreads();
        #pragma unroll
        for (int i = 0; i < 4; i++) {
            int idx = tid + i * THREADS;           // 2048 = 64 rows x 32 cols
            int row = idx >> 5, c = idx & 31;
            stage[row * 33 + c] = x[(size_t)(b0 + row) * NUM_IN + nc0 + c];
        }
        __syncthreads();
        #pragma unroll
        for (int i = 0; i < 2; i++) {
            int idx = tid + i * THREADS;           // 1024 = 32 nodes x 32 words
            int n = idx >> 5, wc = idx & 31;
            float lo = stage[(2 * wc) * 33 + n];
            float hi = stage[(2 * wc + 1) * 33 + n];
            __half2 h = __floats2half2_rn(lo, hi);
            st[(nc0 + n) * WPN + wc] = *(uint32_t*)&h;
        }
    }
    __syncthreads();

    // ---- prefetch round 0 params ----
    if (tid < RSTRIDE / 4) cp16(stage + tid * 4, g_blob + tid * 4);
    asm volatile("cp.async.commit_group;\n");
    asm volatile("cp.async.wait_group 0;\n" ::: "memory");
    __syncthreads();

    uint32_t* stc = st + lane;                     // lane owns cols (2l, 2l+1)

    // ---- main rounds: warp wid evaluates slot wid over 64 columns ----
    for (int r = 0; r < R; r++) {
        float* P  = stage + (r & 1) * RSTRIDE;
        float* Pn = stage + ((r + 1) & 1) * RSTRIDE;
        if (r + 1 < R && tid < RSTRIDE / 4)
            cp16(Pn + tid * 4, g_blob + (size_t)(r + 1) * RSTRIDE + tid * 4);
        asm volatile("cp.async.commit_group;\n");

        const int tgt = ((const int*)P)[784 + wid];
        if (tgt >= 0) {
            const uint4* s4 = (const uint4*)((const unsigned*)P + wid * 16);
            const uint4* w4 = (const uint4*)((const uint32_t*)P + 256 + wid * 32);
            const float  bt = P[768 + wid];

            float z0 = bt, z1 = bt;
            #pragma unroll
            for (int half = 0; half < 2; half++) { // 16 preds per flush group
                __half2 A = __float2half2_rn(0.f);
                __half2 B = __float2half2_rn(0.f);
                __half2 C = __float2half2_rn(0.f);
                __half2 D = __float2half2_rn(0.f);
                #pragma unroll
                for (int h = 0; h < 2; h++) {      // 8 preds per iter
                    uint4 u  = s4[half * 2 + h];
                    uint4 wa = w4[half * 4 + h * 2];
                    uint4 wb = w4[half * 4 + h * 2 + 1];
                    uint32_t v0 = stc[u.x & 0xFFFFu];
                    uint32_t v1 = stc[u.x >> 16];
                    uint32_t v2 = stc[u.y & 0xFFFFu];
                    uint32_t v3 = stc[u.y >> 16];
                    uint32_t v4 = stc[u.z & 0xFFFFu];
                    uint32_t v5 = stc[u.z >> 16];
                    uint32_t v6 = stc[u.w & 0xFFFFu];
                    uint32_t v7 = stc[u.w >> 16];
                    A = __hfma2(u2h(v0), u2h(wa.x), A);
                    B = __hfma2(u2h(v1), u2h(wa.y), B);
                    C = __hfma2(u2h(v2), u2h(wa.z), C);
                    D = __hfma2(u2h(v3), u2h(wa.w), D);
                    A = __hfma2(u2h(v4), u2h(wb.x), A);
                    B = __hfma2(u2h(v5), u2h(wb.y), B);
                    C = __hfma2(u2h(v6), u2h(wb.z), C);
                    D = __hfma2(u2h(v7), u2h(wb.w), D);
                }
                __half2 s = __hadd2(__hadd2(A, B), __hadd2(C, D));
                float2  f = __half22float2(s);
                z0 += f.x;
                z1 += f.y;
            }
            float o0 = __fdividef(1.0f, 1.0f + __expf(-z0));
            float o1 = __fdividef(1.0f, 1.0f + __expf(-z1));
            __half2 hres = __floats2half2_rn(o0, o1);
            stc[tgt] = *(uint32_t*)&hres;
        }

        asm volatile("cp.async.wait_group 0;\n" ::: "memory");
        __syncthreads();
    }

    // ---- output: out[b][j] f32; 2 chunks of 32 output nodes ----
    for (int ch = 0; ch < 2; ch++) {
        const int j0 = ch * 32;
        __syncthreads();
        #pragma unroll
        for (int i = 0; i < 2; i++) {
            int idx = tid + i * THREADS;           // 1024 = 32 j x 32 words
            int j = idx >> 5, wc = idx & 31;
            uint32_t u = st[(NUM_IN + NUM_HID + j0 + j) * WPN + wc];
            float2 v = __half22float2(*(__half2*)&u);
            stage[(2 * wc) * 33 + j]     = v.x;
            stage[(2 * wc + 1) * 33 + j] = v.y;
        }
        __syncthreads();
        #pragma unroll
        for (int i = 0; i < 4; i++) {
            int idx = tid + i * THREADS;           // 2048 = 64 rows x 32 j
            int row = idx >> 5, j = idx & 31;
            out[(size_t)(b0 + row) * NUM_OUT + j0 + j] = stage[row * 33 + j];
        }
    }
}

// ---------------------------------------------------------------------------
extern "C" void kernel_launch(void* const* d_in, const int* in_sizes, int n_in,
                              void* d_out, int out_size) {
    const float* x    = (const float*)d_in[0];
    const float* w    = (const float*)d_in[1];
    const float* bias = (const float*)d_in[2];
    const int*   src  = (const int*)d_in[3];
    float* out = (float*)d_out;
    (void)in_sizes; (void)n_in; (void)out_size;

    cudaFuncSetAttribute(neat_main_kernel,
                         cudaFuncAttributeMaxDynamicSharedMemorySize,
                         TOTAL_WORDS * 4);

    schedule_kernel<<<1, M_NODES>>>(src);
    blob_fill_kernel<<<RMAX, 256>>>(src, w, bias);
    neat_main_kernel<<<BATCH / COLS, THREADS, TOTAL_WORDS * 4>>>(x, out);
}